// round 17
// baseline (speedup 1.0000x reference)
#include <cuda_runtime.h>
#include <cuda_fp16.h>
#include <cstdint>
#include <math.h>

// Problem dimensions (fixed)
constexpr int Bc  = 2;
constexpr int TQc = 512;
constexpr int TKc = 8192;
constexpr int Dc  = 1024;
constexpr int NHc = 16;
constexpr int HDc = 64;

// Scratch (allocation-free)
__device__ float  g_Qp[(size_t)Bc * TQc * Dc];            // Q projected, fp32
__device__ __half g_A16[(size_t)Bc * TKc * Dc];           // kv + group bias, fp16
__device__ __half g_Q16[(size_t)Bc * TQc * Dc];           // q input, fp16
__device__ __half g_Wk16[(size_t)Dc * Dc];
__device__ __half g_Wv16[(size_t)Dc * Dc];
__device__ __half g_Wq16[(size_t)Dc * Dc];
__device__ __half g_Kh[(size_t)Bc * TKc * Dc];            // K projected, fp16
__device__ __half g_Vt[(size_t)Bc * NHc * HDc * TKc];     // V transposed [b,h,dim][key]
__device__ float  g_At[(size_t)Bc * TQc * Dc];            // attention out, fp32

// ---------------------------------------------------------------------------
// helpers
// ---------------------------------------------------------------------------
__device__ __forceinline__ uint32_t pack_h2(float lo, float hi) {
    __half2 h = __floats2half2_rn(lo, hi);
    return *reinterpret_cast<uint32_t*>(&h);
}

__device__ __forceinline__ void mma_f16(float& c0, float& c1, float& c2, float& c3,
                                        uint32_t a0, uint32_t a1, uint32_t a2, uint32_t a3,
                                        uint32_t b0, uint32_t b1)
{
    asm volatile(
        "mma.sync.aligned.m16n8k16.row.col.f32.f16.f16.f32 "
        "{%0,%1,%2,%3}, {%4,%5,%6,%7}, {%8,%9}, {%0,%1,%2,%3};"
        : "+f"(c0), "+f"(c1), "+f"(c2), "+f"(c3)
        : "r"(a0), "r"(a1), "r"(a2), "r"(a3), "r"(b0), "r"(b1));
}

__device__ __forceinline__ void ldsm_x4(uint32_t& r0, uint32_t& r1,
                                        uint32_t& r2, uint32_t& r3, uint32_t addr)
{
    asm volatile("ldmatrix.sync.aligned.m8n8.x4.shared.b16 {%0,%1,%2,%3}, [%4];"
                 : "=r"(r0), "=r"(r1), "=r"(r2), "=r"(r3) : "r"(addr));
}

__device__ __forceinline__ void cp16(uint32_t dst, const void* src) {
    asm volatile("cp.async.cg.shared.global [%0], [%1], 16;" :: "r"(dst), "l"(src));
}
__device__ __forceinline__ void cp16z(uint32_t dst, const void* src, int srcsz) {
    asm volatile("cp.async.cg.shared.global [%0], [%1], 16, %2;"
                 :: "r"(dst), "l"(src), "r"(srcsz));
}
__device__ __forceinline__ void cp_commit() { asm volatile("cp.async.commit_group;"); }
template <int N>
__device__ __forceinline__ void cp_wait() { asm volatile("cp.async.wait_group %0;" :: "n"(N)); }

// swizzled u32 index, fp16 tile, row stride 64 halves (32 u32)
__device__ __forceinline__ int sw_idx64(int row, int gbase, int cc) {
    return row * 32 + ((gbase ^ (row & 7)) << 2) + cc;
}

// ---------------------------------------------------------------------------
// prep: kv(fp32) + group bias -> fp16 ; fp32 -> fp16 for Wk/Wv/Wq/q (y=0..3)
// ---------------------------------------------------------------------------
__global__ __launch_bounds__(256)
void prep_kv(const float* __restrict__ kv, const float* __restrict__ abA,
             const float* __restrict__ abI, const int* __restrict__ pNA,
             __half* __restrict__ dst)
{
    const int na = *pNA;
    const size_t i8 = (size_t)(blockIdx.x * 256 + threadIdx.x) * 8;
    const int row = (int)(i8 >> 10);
    const int col = (int)(i8 & 1023);
    const float* ab = ((row % TKc) < na) ? abA : abI;
    float4 v0 = *reinterpret_cast<const float4*>(kv + i8);
    float4 v1 = *reinterpret_cast<const float4*>(kv + i8 + 4);
    float4 b0 = *reinterpret_cast<const float4*>(ab + col);
    float4 b1 = *reinterpret_cast<const float4*>(ab + col + 4);
    uint4 o;
    o.x = pack_h2(v0.x + b0.x, v0.y + b0.y);
    o.y = pack_h2(v0.z + b0.z, v0.w + b0.w);
    o.z = pack_h2(v1.x + b1.x, v1.y + b1.y);
    o.w = pack_h2(v1.z + b1.z, v1.w + b1.w);
    *reinterpret_cast<uint4*>(dst + i8) = o;
}

__global__ __launch_bounds__(256)
void prep_w4(const float* __restrict__ s0, const float* __restrict__ s1,
             const float* __restrict__ s2, const float* __restrict__ s3,
             __half* __restrict__ d0, __half* __restrict__ d1,
             __half* __restrict__ d2, __half* __restrict__ d3)
{
    const float* src; __half* dst;
    switch (blockIdx.y) {
        case 0:  src = s0; dst = d0; break;
        case 1:  src = s1; dst = d1; break;
        case 2:  src = s2; dst = d2; break;
        default: src = s3; dst = d3; break;
    }
    const size_t i8 = (size_t)(blockIdx.x * 256 + threadIdx.x) * 8;
    float4 v0 = *reinterpret_cast<const float4*>(src + i8);
    float4 v1 = *reinterpret_cast<const float4*>(src + i8 + 4);
    uint4 o;
    o.x = pack_h2(v0.x, v0.y); o.y = pack_h2(v0.z, v0.w);
    o.z = pack_h2(v1.x, v1.y); o.w = pack_h2(v1.z, v1.w);
    *reinterpret_cast<uint4*>(dst + i8) = o;
}

// ---------------------------------------------------------------------------
// Unified projection GEMM, cp.async 3-stage pipelined, one barrier/stage.
//  blockIdx.y <  128 : K+V rows (fused dual-output, V written TRANSPOSED)
//  blockIdx.y >= 128 : Q rows   (single output, fp32 into Qp) — rides the
//                      same launch so Q-projection runs concurrently.
// BM=BN=128, BK=64, 512 threads, warp tile 32x32. Smem 3 x 48KB = 144 KB.
// ---------------------------------------------------------------------------
constexpr int KV_STAGE_H = 3 * 128 * 64;                // halves per stage
constexpr int KV_SMEM_BYTES = 3 * KV_STAGE_H * 2;       // 144 KB

__global__ __launch_bounds__(512)
void qkvgemm(const __half* __restrict__ A, const __half* __restrict__ Q16,
             const __half* __restrict__ Wk, const __half* __restrict__ Wv,
             const __half* __restrict__ Wq,
             const float* __restrict__ bk, const float* __restrict__ bv,
             const float* __restrict__ bq,
             __half* __restrict__ CK, __half* __restrict__ Vt,
             float* __restrict__ Qp)
{
    extern __shared__ __half sm[];

    const int tid  = threadIdx.x;
    const int warp = tid >> 5;
    const int lane = tid & 31;
    const int gr   = lane >> 2;
    const int cc   = lane & 3;
    const int lr   = lane & 7;
    const int lmh  = lane >> 4;
    const int lml  = (lane >> 3) & 1;
    const int wm   = (warp >> 2) * 32;
    const int wn   = (warp & 3) * 32;
    const bool isQ = (blockIdx.y >= 128);
    const int m0   = (isQ ? ((int)blockIdx.y - 128) : (int)blockIdx.y) * 128;
    const int n0   = blockIdx.x * 128;

    const __half* Ap = isQ ? Q16 : A;
    const __half* Bp = isQ ? Wq  : Wk;

    const uint32_t smBase = (uint32_t)__cvta_generic_to_shared(sm);

    float accK[2][4][4], accV[2][4][4];
#pragma unroll
    for (int mt = 0; mt < 2; mt++)
#pragma unroll
        for (int nt = 0; nt < 4; nt++)
#pragma unroll
            for (int r = 0; r < 4; r++) { accK[mt][nt][r] = 0.f; accV[mt][nt][r] = 0.f; }

    auto issue_stage = [&](int k0, int st) {
        const uint32_t sa = smBase + (uint32_t)(st * KV_STAGE_H) * 2;
        const uint32_t sk = sa + 128 * 64 * 2;
        const uint32_t sv = sk + 128 * 64 * 2;
#pragma unroll
        for (int p = 0; p < 2; p++) {
            const int idx = tid + p * 512;
            const int r   = idx >> 3;
            const int g0  = idx & 7;
            const uint32_t off = (uint32_t)(r * 128 + ((g0 ^ (r & 7)) << 4));
            const size_t goff = (size_t)g0 * 8 + k0;
            cp16(sa + off, Ap + (size_t)(m0 + r) * Dc + goff);
            cp16(sk + off, Bp + (size_t)(n0 + r) * Dc + goff);
            if (!isQ) cp16(sv + off, Wv + (size_t)(n0 + r) * Dc + goff);
        }
        cp_commit();
    };

    issue_stage(0, 0);
    issue_stage(64, 1);

    constexpr int NSTAGES = Dc / 64;   // 16
    for (int it = 0; it < NSTAGES; it++) {
        if (it < NSTAGES - 1) cp_wait<1>();
        else                  cp_wait<0>();
        __syncthreads();
        if (it + 2 < NSTAGES) issue_stage((it + 2) * 64, (it + 2) % 3);

        const int st = it % 3;
        const uint32_t aBase = smBase + (uint32_t)(st * KV_STAGE_H) * 2;
        const uint32_t kBase = aBase + 128 * 64 * 2;
        const uint32_t vBase = kBase + 128 * 64 * 2;

#pragma unroll
        for (int ks = 0; ks < 4; ks++) {
            uint32_t af[2][4];
#pragma unroll
            for (int mt = 0; mt < 2; mt++) {
                const int r  = wm + mt * 16 + lml * 8 + lr;
                const int lg = 2 * ks + lmh;
                ldsm_x4(af[mt][0], af[mt][1], af[mt][2], af[mt][3],
                        aBase + (uint32_t)(r * 128 + ((lg ^ (r & 7)) << 4)));
            }
            uint32_t bkf[8], bvf[8];
#pragma unroll
            for (int j = 0; j < 2; j++) {
                const int n  = wn + (2 * j + lmh) * 8 + lr;
                const int lg = 2 * ks + lml;
                const uint32_t off = (uint32_t)(n * 128 + ((lg ^ (n & 7)) << 4));
                ldsm_x4(bkf[4 * j], bkf[4 * j + 1], bkf[4 * j + 2], bkf[4 * j + 3], kBase + off);
                if (!isQ)
                    ldsm_x4(bvf[4 * j], bvf[4 * j + 1], bvf[4 * j + 2], bvf[4 * j + 3], vBase + off);
            }
#pragma unroll
            for (int nt = 0; nt < 4; nt++) {
                const int bi = 4 * (nt >> 1) + 2 * (nt & 1);
#pragma unroll
                for (int mt = 0; mt < 2; mt++) {
                    mma_f16(accK[mt][nt][0], accK[mt][nt][1], accK[mt][nt][2], accK[mt][nt][3],
                            af[mt][0], af[mt][1], af[mt][2], af[mt][3], bkf[bi], bkf[bi + 1]);
                    if (!isQ)
                        mma_f16(accV[mt][nt][0], accV[mt][nt][1], accV[mt][nt][2], accV[mt][nt][3],
                                af[mt][0], af[mt][1], af[mt][2], af[mt][3], bvf[bi], bvf[bi + 1]);
                }
            }
        }
    }
    __syncthreads();   // all warps done with final stage before smem reuse

    if (isQ) {
        // Q epilogue: bias + fp32 store into Qp
#pragma unroll
        for (int mt = 0; mt < 2; mt++) {
#pragma unroll
            for (int nt = 0; nt < 4; nt++) {
                const int row = m0 + wm + mt * 16 + gr;
                const int col = n0 + wn + nt * 8 + 2 * cc;
                const float b0v = bq[col], b1v = bq[col + 1];
                *reinterpret_cast<float2*>(Qp + (size_t)row * Dc + col) =
                    make_float2(accK[mt][nt][0] + b0v, accK[mt][nt][1] + b1v);
                *reinterpret_cast<float2*>(Qp + (size_t)(row + 8) * Dc + col) =
                    make_float2(accK[mt][nt][2] + b0v, accK[mt][nt][3] + b1v);
            }
        }
        return;
    }

    // epilogue 1: K direct (row-major fp16), accV staged transposed into smem
    constexpr int LDV = 136;
    __half* VsT = sm;          // stage-0 smem: [128 dims][LDV] = 34816 B
#pragma unroll
    for (int mt = 0; mt < 2; mt++) {
#pragma unroll
        for (int nt = 0; nt < 4; nt++) {
            const int rl  = wm + mt * 16 + gr;
            const int cl  = wn + nt * 8 + 2 * cc;
            const int row = m0 + rl;
            const int col = n0 + cl;
            const float bk0 = bk[col], bk1 = bk[col + 1];
            const float bv0 = bv[col], bv1 = bv[col + 1];
            __half2* CKp = (__half2*)CK;
            CKp[((size_t)row * Dc + col) >> 1] =
                __floats2half2_rn(accK[mt][nt][0] + bk0, accK[mt][nt][1] + bk1);
            CKp[((size_t)(row + 8) * Dc + col) >> 1] =
                __floats2half2_rn(accK[mt][nt][2] + bk0, accK[mt][nt][3] + bk1);
            VsT[(cl)     * LDV + rl]     = __float2half_rn(accV[mt][nt][0] + bv0);
            VsT[(cl + 1) * LDV + rl]     = __float2half_rn(accV[mt][nt][1] + bv1);
            VsT[(cl)     * LDV + rl + 8] = __float2half_rn(accV[mt][nt][2] + bv0);
            VsT[(cl + 1) * LDV + rl + 8] = __float2half_rn(accV[mt][nt][3] + bv1);
        }
    }
    __syncthreads();

    // epilogue 2: coalesced transposed V write: Vt[(b*16+h)*64+d][key]
    const int bb   = m0 >> 13;
    const int key0 = m0 & (TKc - 1);
#pragma unroll
    for (int p = 0; p < 4; p++) {
        const int idx = tid + p * 512;
        const int dl  = idx >> 4;
        const int kc  = idx & 15;
        const int gd  = n0 + dl;
        const int h   = gd >> 6;
        const int d   = gd & 63;
        uint4 v = *reinterpret_cast<const uint4*>(&VsT[dl * LDV + kc * 8]);
        *reinterpret_cast<uint4*>(
            Vt + ((size_t)((bb * NHc + h) * HDc + d)) * TKc + key0 + kc * 8) = v;
    }
}

// ---------------------------------------------------------------------------
// fp16 GEMM for the O projection, BM=64 x BN=128 (unchanged).
// ---------------------------------------------------------------------------
__global__ __launch_bounds__(256)
void gemm16b(const float* __restrict__ A, const float* __restrict__ W,
             const float* __restrict__ bias, float* __restrict__ C,
             int M, int N, int K)
{
    __shared__ __half As[64 * 64];
    __shared__ __half Bs[128 * 64];
    uint32_t* As32 = reinterpret_cast<uint32_t*>(As);
    uint32_t* Bs32 = reinterpret_cast<uint32_t*>(Bs);

    const int tid  = threadIdx.x;
    const int warp = tid >> 5;
    const int lane = tid & 31;
    const int gr   = lane >> 2;
    const int cc   = lane & 3;
    const int wm   = (warp >> 2) * 32;
    const int wn   = (warp & 3) * 32;
    const int m0   = blockIdx.y * 64;
    const int n0   = blockIdx.x * 128;

    float acc[2][4][4];
#pragma unroll
    for (int mt = 0; mt < 2; mt++)
#pragma unroll
        for (int nt = 0; nt < 4; nt++)
#pragma unroll
            for (int r = 0; r < 4; r++) acc[mt][nt][r] = 0.f;

    float4 rA[4], rB[8];
    auto load_tiles = [&](int k0) {
#pragma unroll
        for (int p = 0; p < 2; p++) {
            const int idx = tid + p * 256;
            const int r   = idx >> 3;
            const int gk  = k0 + (idx & 7) * 8;
            const float* ap = A + (size_t)(m0 + r) * K + gk;
            rA[p * 2]     = *reinterpret_cast<const float4*>(ap);
            rA[p * 2 + 1] = *reinterpret_cast<const float4*>(ap + 4);
        }
#pragma unroll
        for (int p = 0; p < 4; p++) {
            const int idx = tid + p * 256;
            const int r   = idx >> 3;
            const int gk  = k0 + (idx & 7) * 8;
            const float* wp = W + (size_t)(n0 + r) * K + gk;
            rB[p * 2]     = *reinterpret_cast<const float4*>(wp);
            rB[p * 2 + 1] = *reinterpret_cast<const float4*>(wp + 4);
        }
    };
    auto store_tiles = [&]() {
#pragma unroll
        for (int p = 0; p < 2; p++) {
            const int idx = tid + p * 256;
            const int r   = idx >> 3;
            const int g   = (idx & 7) ^ (r & 7);
            float4 a0 = rA[p * 2], a1 = rA[p * 2 + 1];
            uint4 ua;
            ua.x = pack_h2(a0.x, a0.y); ua.y = pack_h2(a0.z, a0.w);
            ua.z = pack_h2(a1.x, a1.y); ua.w = pack_h2(a1.z, a1.w);
            *reinterpret_cast<uint4*>(&As[r * 64 + g * 8]) = ua;
        }
#pragma unroll
        for (int p = 0; p < 4; p++) {
            const int idx = tid + p * 256;
            const int r   = idx >> 3;
            const int g   = (idx & 7) ^ (r & 7);
            float4 b0 = rB[p * 2], b1 = rB[p * 2 + 1];
            uint4 ub;
            ub.x = pack_h2(b0.x, b0.y); ub.y = pack_h2(b0.z, b0.w);
            ub.z = pack_h2(b1.x, b1.y); ub.w = pack_h2(b1.z, b1.w);
            *reinterpret_cast<uint4*>(&Bs[r * 64 + g * 8]) = ub;
        }
    };

    load_tiles(0);
    for (int k0 = 0; k0 < K; k0 += 64) {
        store_tiles();
        __syncthreads();
        if (k0 + 64 < K) load_tiles(k0 + 64);
#pragma unroll
        for (int ks = 0; ks < 4; ks++) {
            uint32_t af[2][4];
#pragma unroll
            for (int mt = 0; mt < 2; mt++) {
                const int r = wm + mt * 16 + gr;
                af[mt][0] = As32[sw_idx64(r,     2 * ks,     cc)];
                af[mt][1] = As32[sw_idx64(r + 8, 2 * ks,     cc)];
                af[mt][2] = As32[sw_idx64(r,     2 * ks + 1, cc)];
                af[mt][3] = As32[sw_idx64(r + 8, 2 * ks + 1, cc)];
            }
#pragma unroll
            for (int nt = 0; nt < 4; nt++) {
                const int n = wn + nt * 8 + gr;
                uint32_t b0 = Bs32[sw_idx64(n, 2 * ks,     cc)];
                uint32_t b1 = Bs32[sw_idx64(n, 2 * ks + 1, cc)];
#pragma unroll
                for (int mt = 0; mt < 2; mt++)
                    mma_f16(acc[mt][nt][0], acc[mt][nt][1], acc[mt][nt][2], acc[mt][nt][3],
                            af[mt][0], af[mt][1], af[mt][2], af[mt][3], b0, b1);
            }
        }
        __syncthreads();
    }

#pragma unroll
    for (int mt = 0; mt < 2; mt++) {
#pragma unroll
        for (int nt = 0; nt < 4; nt++) {
            const int row = m0 + wm + mt * 16 + gr;
            const int col = n0 + wn + nt * 8 + 2 * cc;
            const float b0v = bias[col], b1v = bias[col + 1];
            *reinterpret_cast<float2*>(C + (size_t)row * N + col) =
                make_float2(acc[mt][nt][0] + b0v, acc[mt][nt][1] + b1v);
            *reinterpret_cast<float2*>(C + (size_t)(row + 8) * N + col) =
                make_float2(acc[mt][nt][2] + b0v, acc[mt][nt][3] + b1v);
        }
    }
}

// ---------------------------------------------------------------------------
// fp16 MMA flash attention (unchanged): cp.async double-buffered TS=64.
// ---------------------------------------------------------------------------
constexpr int TSa = 64;

__global__ __launch_bounds__(256)
void attn_f16(const float* __restrict__ Qp, const __half* __restrict__ Kh,
              const __half* __restrict__ Vt, float* __restrict__ At,
              const float* __restrict__ p_log_temp, const int* __restrict__ pNA)
{
    __shared__ __half Ks[2][64 * 64];
    __shared__ __half VtS[2][64 * 64];

    const int b    = blockIdx.z;
    const int h    = blockIdx.y;
    const int q0   = blockIdx.x * 128;
    const int tid  = threadIdx.x;
    const int warp = tid >> 5;
    const int lane = tid & 31;
    const int gr   = lane >> 2;
    const int cc   = lane & 3;
    const int lr   = lane & 7;
    const int lmh  = lane >> 4;
    const int lml  = (lane >> 3) & 1;
    const int rl   = warp * 16 + gr;
    const int row0 = q0 + rl;

    const uint32_t ksBase  = (uint32_t)__cvta_generic_to_shared(&Ks[0][0]);
    const uint32_t vtsBase = (uint32_t)__cvta_generic_to_shared(&VtS[0][0]);

    const int na = *pNA;
    float temp = __expf(*p_log_temp);
    temp = fminf(fmaxf(temp, 0.1f), 10.0f);
    const float scale = 1.0f / ((float)HDc * temp);

    uint32_t qf[4][4];
    {
        const float* qr0 = Qp + ((size_t)(b * TQc + row0)) * Dc + h * HDc;
        const float* qr1 = qr0 + 8 * (size_t)Dc;
#pragma unroll
        for (int ks = 0; ks < 4; ks++) {
            const int k = ks * 16;
            float2 a  = *reinterpret_cast<const float2*>(qr0 + k + 2 * cc);
            float2 bv = *reinterpret_cast<const float2*>(qr1 + k + 2 * cc);
            float2 c2 = *reinterpret_cast<const float2*>(qr0 + k + 8 + 2 * cc);
            float2 d2 = *reinterpret_cast<const float2*>(qr1 + k + 8 + 2 * cc);
            qf[ks][0] = pack_h2(a.x * scale, a.y * scale);
            qf[ks][1] = pack_h2(bv.x * scale, bv.y * scale);
            qf[ks][2] = pack_h2(c2.x * scale, c2.y * scale);
            qf[ks][3] = pack_h2(d2.x * scale, d2.y * scale);
        }
    }

    float outc[8][4];
#pragma unroll
    for (int nt = 0; nt < 8; nt++)
#pragma unroll
        for (int r = 0; r < 4; r++) outc[nt][r] = 0.f;

    const int lrow = tid >> 3;
    const int seg  = tid & 7;

    auto issue_tile = [&](int kbase, int valid, int st) {
        const uint32_t ksSt = ksBase  + (uint32_t)st * 8192;
        const uint32_t vtSt = vtsBase + (uint32_t)st * 8192;
#pragma unroll
        for (int p = 0; p < 2; p++) {
            const int r = lrow + p * 32;
            const int g = seg ^ (r & 7);
            const int srcsz = (r < valid) ? 16 : 0;
            const int gkey  = kbase + ((r < valid) ? r : 0);
            cp16z(ksSt + (uint32_t)(r * 128 + g * 16),
                  Kh + ((size_t)(b * TKc + gkey)) * Dc + h * HDc + seg * 8, srcsz);
        }
#pragma unroll
        for (int p = 0; p < 2; p++) {
            const int r = lrow + p * 32;
            const int g = seg ^ (r & 7);
            int srcsz = (valid - seg * 8) * 2;
            srcsz = srcsz < 0 ? 0 : (srcsz > 16 ? 16 : srcsz);
            cp16z(vtSt + (uint32_t)(r * 128 + g * 16),
                  Vt + ((size_t)((b * NHc + h) * HDc + r)) * TKc + kbase + seg * 8, srcsz);
        }
        cp_commit();
    };

    for (int segi = 0; segi < 2; segi++) {
        const int s_begin = segi ? na : 0;
        const int s_end   = segi ? TKc : na;
        const int s_cnt   = s_end - s_begin;
        if (s_cnt <= 0) continue;
        const float coef = (segi ? -1.f : 1.f) / sqrtf((float)s_cnt);

        float l0 = 0.f, l1 = 0.f;
        float o[8][4];
#pragma unroll
        for (int nt = 0; nt < 8; nt++)
#pragma unroll
            for (int r = 0; r < 4; r++) o[nt][r] = 0.f;

        const int ntiles = (s_cnt + TSa - 1) / TSa;
        issue_tile(s_begin, min(TSa, s_cnt), 0);

        for (int tile = 0; tile < ntiles; tile++) {
            const int kbase = s_begin + tile * TSa;
            const int valid = min(TSa, s_end - kbase);
            const bool partial = (valid < TSa);
            const int st = tile & 1;

            if (tile + 1 < ntiles) {
                const int kb2 = kbase + TSa;
                issue_tile(kb2, min(TSa, s_end - kb2), (tile + 1) & 1);
                cp_wait<1>();
            } else {
                cp_wait<0>();
            }
            __syncthreads();

            const uint32_t ksSt = ksBase  + (uint32_t)st * 8192;
            const uint32_t vtSt = vtsBase + (uint32_t)st * 8192;

            float sacc[8][4];
#pragma unroll
            for (int nt = 0; nt < 8; nt++)
#pragma unroll
                for (int r = 0; r < 4; r++) sacc[nt][r] = 0.f;
#pragma unroll
            for (int ks = 0; ks < 4; ks++) {
#pragma unroll
                for (int j = 0; j < 4; j++) {
                    const int n  = (2 * j + lmh) * 8 + lr;
                    const int lg = 2 * ks + lml;
                    uint32_t f0, f1, f2, f3;
                    ldsm_x4(f0, f1, f2, f3,
                            ksSt + (uint32_t)(n * 128 + ((lg ^ (n & 7)) << 4)));
                    mma_f16(sacc[2*j][0], sacc[2*j][1], sacc[2*j][2], sacc[2*j][3],
                            qf[ks][0], qf[ks][1], qf[ks][2], qf[ks][3], f0, f1);
                    mma_f16(sacc[2*j+1][0], sacc[2*j+1][1], sacc[2*j+1][2], sacc[2*j+1][3],
                            qf[ks][0], qf[ks][1], qf[ks][2], qf[ks][3], f2, f3);
                }
            }

            if (partial) {
#pragma unroll
                for (int nt = 0; nt < 8; nt++) {
                    const int col = nt * 8 + 2 * cc;
                    if (col     >= valid) { sacc[nt][0] = -INFINITY; sacc[nt][2] = -INFINITY; }
                    if (col + 1 >= valid) { sacc[nt][1] = -INFINITY; sacc[nt][3] = -INFINITY; }
                }
            }

            uint32_t ap[4][4];
#pragma unroll
            for (int nt = 0; nt < 8; nt++) {
                float p0 = __expf(sacc[nt][0]);
                float p1 = __expf(sacc[nt][1]);
                float p2 = __expf(sacc[nt][2]);
                float p3 = __expf(sacc[nt][3]);
                l0 += p0 + p1;
                l1 += p2 + p3;
                const int kt   = nt >> 1;
                const int half = nt & 1;
                ap[kt][half * 2]     = pack_h2(p0, p1);
                ap[kt][half * 2 + 1] = pack_h2(p2, p3);
            }

#pragma unroll
            for (int kt = 0; kt < 4; kt++) {
#pragma unroll
                for (int j = 0; j < 4; j++) {
                    const int n  = (2 * j + lmh) * 8 + lr;
                    const int lg = 2 * kt + lml;
                    uint32_t f0, f1, f2, f3;
                    ldsm_x4(f0, f1, f2, f3,
                            vtSt + (uint32_t)(n * 128 + ((lg ^ (n & 7)) << 4)));
                    mma_f16(o[2*j][0], o[2*j][1], o[2*j][2], o[2*j][3],
                            ap[kt][0], ap[kt][1], ap[kt][2], ap[kt][3], f0, f1);
                    mma_f16(o[2*j+1][0], o[2*j+1][1], o[2*j+1][2], o[2*j+1][3],
                            ap[kt][0], ap[kt][1], ap[kt][2], ap[kt][3], f2, f3);
                }
            }
            __syncthreads();
        }

        l0 += __shfl_xor_sync(0xffffffffu, l0, 1);
        l0 += __shfl_xor_sync(0xffffffffu, l0, 2);
        l1 += __shfl_xor_sync(0xffffffffu, l1, 1);
        l1 += __shfl_xor_sync(0xffffffffu, l1, 2);
        const float inv0 = coef / l0;
        const float inv1 = coef / l1;
#pragma unroll
        for (int nt = 0; nt < 8; nt++) {
            outc[nt][0] += o[nt][0] * inv0;
            outc[nt][1] += o[nt][1] * inv0;
            outc[nt][2] += o[nt][2] * inv1;
            outc[nt][3] += o[nt][3] * inv1;
        }
    }

    float* ob = At + ((size_t)(b * TQc + row0)) * Dc + h * HDc;
#pragma unroll
    for (int nt = 0; nt < 8; nt++) {
        const int col = nt * 8 + 2 * cc;
        *reinterpret_cast<float2*>(ob + col) = make_float2(outc[nt][0], outc[nt][1]);
        *reinterpret_cast<float2*>(ob + 8 * (size_t)Dc + col) = make_float2(outc[nt][2], outc[nt][3]);
    }
}

// ---------------------------------------------------------------------------
// kernel_launch
// ---------------------------------------------------------------------------
extern "C" void kernel_launch(void* const* d_in, const int* in_sizes, int n_in,
                              void* d_out, int out_size)
{
    const float* q    = (const float*)d_in[0];
    const float* kv   = (const float*)d_in[1];
    const float* Wq   = (const float*)d_in[2];
    const float* bq   = (const float*)d_in[3];
    const float* Wk   = (const float*)d_in[4];
    const float* bk   = (const float*)d_in[5];
    const float* Wv   = (const float*)d_in[6];
    const float* bv   = (const float*)d_in[7];
    const float* Wo   = (const float*)d_in[8];
    const float* bo   = (const float*)d_in[9];
    const float* abA  = (const float*)d_in[10];
    const float* abI  = (const float*)d_in[11];
    const float* logt = (const float*)d_in[12];
    const int*   pNA  = (const int*)d_in[13];
    float* out = (float*)d_out;

    void *pQp, *pA16, *pQ16, *pWk16, *pWv16, *pWq16, *pKh, *pVt, *pAt;
    cudaGetSymbolAddress(&pQp,   g_Qp);
    cudaGetSymbolAddress(&pA16,  g_A16);
    cudaGetSymbolAddress(&pQ16,  g_Q16);
    cudaGetSymbolAddress(&pWk16, g_Wk16);
    cudaGetSymbolAddress(&pWv16, g_Wv16);
    cudaGetSymbolAddress(&pWq16, g_Wq16);
    cudaGetSymbolAddress(&pKh,   g_Kh);
    cudaGetSymbolAddress(&pVt,   g_Vt);
    cudaGetSymbolAddress(&pAt,   g_At);

    // opt-in to >48KB dynamic smem for the pipelined projection kernel
    cudaFuncSetAttribute(qkvgemm, cudaFuncAttributeMaxDynamicSharedMemorySize,
                         KV_SMEM_BYTES);

    const dim3 gblk(256);

    // prep: kv + group bias -> fp16; Wk/Wv/Wq/q -> fp16 (one launch)
    prep_kv<<<(Bc * TKc * Dc) / (256 * 8), gblk>>>(kv, abA, abI, pNA, (__half*)pA16);
    prep_w4<<<dim3((Dc * Dc) / (256 * 8), 4), gblk>>>(
        Wk, Wv, Wq, q,
        (__half*)pWk16, (__half*)pWv16, (__half*)pWq16, (__half*)pQ16);

    // unified projections: y<128 K+V (V transposed), y>=128 Q (fp32 out)
    qkvgemm<<<dim3(Dc / 128, 136), dim3(512), KV_SMEM_BYTES>>>(
        (const __half*)pA16, (const __half*)pQ16,
        (const __half*)pWk16, (const __half*)pWv16, (const __half*)pWq16,
        bk, bv, bq, (__half*)pKh, (__half*)pVt, (float*)pQp);

    attn_f16<<<dim3(TQc / 128, NHc, Bc), gblk>>>(
        (const float*)pQp, (const __half*)pKh, (const __half*)pVt, (float*)pAt,
        logt, pNA);

    gemm16b<<<dim3(Dc / 128, (Bc * TQc) / 64), gblk>>>(
        (const float*)pAt, Wo, bo, out, Bc * TQc, Dc, Dc);
}